// round 9
// baseline (speedup 1.0000x reference)
#include <cuda_runtime.h>
#include <cuda_bf16.h>
#include <cstdint>
#include <math.h>

#define BATCH 32768
#define DIM   1024
#define HID   256

typedef __nv_bfloat16 bf16;
typedef unsigned long long ull;

// ---------------- device scratch (no runtime allocation) -------------------
// 3-way exact bf16 split planes (hi, mid, lo): 8+8+8 mantissa bits >= fp32's 24
__device__ bf16 g_F0[(size_t)BATCH * DIM];
__device__ bf16 g_F1[(size_t)BATCH * DIM];
__device__ bf16 g_F2[(size_t)BATCH * DIM];
__device__ bf16 g_H0[(size_t)BATCH * HID];
__device__ bf16 g_H1[(size_t)BATCH * HID];
__device__ bf16 g_H2[(size_t)BATCH * HID];
__device__ bf16 g_W10[DIM * HID], g_W11[DIM * HID], g_W12[DIM * HID]; // [N=256][K=1024]
__device__ bf16 g_W20[HID * DIM], g_W21[HID * DIM], g_W22[HID * DIM]; // [N=1024][K=256]
__device__ float g_comp[(size_t)BATCH * DIM];  // 128 MB

__device__ __forceinline__ float sigmoidf_(float x) {
    return 1.0f / (1.0f + expf(-x));
}

__device__ __forceinline__ void split3(float x, bf16& h, bf16& m, bf16& l) {
    h = __float2bfloat16_rn(x);
    float r1 = x - __bfloat162float(h);     // exact in fp32
    m = __float2bfloat16_rn(r1);
    float r2 = r1 - __bfloat162float(m);    // exact in fp32
    l = __float2bfloat16_rn(r2);
}

__device__ __forceinline__ void cp16(void* s, const void* gp) {
    uint32_t sa = (uint32_t)__cvta_generic_to_shared(s);
    asm volatile("cp.async.cg.shared.global [%0], [%1], 16;\n" :: "r"(sa), "l"(gp));
}
#define CP_COMMIT() asm volatile("cp.async.commit_group;\n")
#define CP_WAIT1()  asm volatile("cp.async.wait_group 1;\n")
#define CP_WAIT0()  asm volatile("cp.async.wait_group 0;\n")

__device__ __forceinline__ void mma16816(float* d, const uint32_t* a, const uint32_t* b) {
    asm volatile(
        "mma.sync.aligned.m16n8k16.row.col.f32.bf16.bf16.f32 "
        "{%0,%1,%2,%3}, {%4,%5,%6,%7}, {%8,%9}, {%0,%1,%2,%3};\n"
        : "+f"(d[0]), "+f"(d[1]), "+f"(d[2]), "+f"(d[3])
        : "r"(a[0]), "r"(a[1]), "r"(a[2]), "r"(a[3]), "r"(b[0]), "r"(b[1]));
}

// IEEE-rn packed fp32 add (two independent scalar rn-adds)
__device__ __forceinline__ void fadd2(ull& d, ull a) {
    asm("add.rn.f32x2 %0, %0, %1;" : "+l"(d) : "l"(a));
}
__device__ __forceinline__ ull pack2(float lo, float hi) {
    ull r;
    asm("mov.b64 %0, {%1, %2};" : "=l"(r) : "f"(lo), "f"(hi));
    return r;
}
__device__ __forceinline__ void unpack2(ull v, float& lo, float& hi) {
    asm("mov.b64 {%0, %1}, %2;" : "=f"(lo), "=f"(hi) : "l"(v));
}

// ---------------- conversion kernels ---------------------------------------
__global__ __launch_bounds__(256) void cvt_f_k(const float* __restrict__ x) {
    size_t i = ((size_t)blockIdx.x * 256 + threadIdx.x) * 4;
    float4 v = *(const float4*)(x + i);
    bf16 h[4], m[4], l[4];
    split3(v.x, h[0], m[0], l[0]);
    split3(v.y, h[1], m[1], l[1]);
    split3(v.z, h[2], m[2], l[2]);
    split3(v.w, h[3], m[3], l[3]);
    *(__nv_bfloat162*)(g_F0 + i)     = __nv_bfloat162(h[0], h[1]);
    *(__nv_bfloat162*)(g_F0 + i + 2) = __nv_bfloat162(h[2], h[3]);
    *(__nv_bfloat162*)(g_F1 + i)     = __nv_bfloat162(m[0], m[1]);
    *(__nv_bfloat162*)(g_F1 + i + 2) = __nv_bfloat162(m[2], m[3]);
    *(__nv_bfloat162*)(g_F2 + i)     = __nv_bfloat162(l[0], l[1]);
    *(__nv_bfloat162*)(g_F2 + i + 2) = __nv_bfloat162(l[2], l[3]);
}

__global__ __launch_bounds__(256) void cvt_w_k(const float* __restrict__ w,
                                               bf16* __restrict__ w0,
                                               bf16* __restrict__ w1,
                                               bf16* __restrict__ w2,
                                               int K, int N) {
    int i = blockIdx.x * 256 + threadIdx.x;
    if (i >= K * N) return;
    int k = i / N, n = i % N;
    bf16 h, m, l;
    split3(w[i], h, m, l);
    w0[(size_t)n * K + k] = h;
    w1[(size_t)n * K + k] = m;
    w2[(size_t)n * K + k] = l;
}

// ---------------- tensor-core GEMM with register accumulation ---------------
// C[M,N] = epi(A @ W + bias). 3-plane bf16 inputs (exact split).
// Per 16-k chunk:
//   hh term:   MMA with C=0, result added to register acc via add.rn.f32x2
//              (NO long hardware D-chains -> no truncating-accumulate noise,
//               cross-chunk sum is a clean fp32-rn chain, noise ~2e-7)
//   5 corr terms (hm,hl,mh,mm,lh): chained in D only WITHIN the chunk
//              (depth 5, scale <=2^-9 -> harmless), extracted per chunk.
// Final x = accA + accC + bias.
// CTA 128x64, 8 warps as 2(M)x4(N), warp tile 64x16 (mt 0..3, nt 0..1).
#define BM 128
#define BN 64
#define BK 16
#define SPAD 24
#define STAGE_HALVES (3 * (BM + BN) * SPAD)     // 13824 bf16 per stage
#define SMEM_BYTES   (2 * STAGE_HALVES * 2)     // 55296 B

template <int EPI, int K, int N>
__global__ __launch_bounds__(256, 1) void gemm_tc(
    const bf16* __restrict__ A0g, const bf16* __restrict__ A1g, const bf16* __restrict__ A2g,
    const bf16* __restrict__ B0g, const bf16* __restrict__ B1g, const bf16* __restrict__ B2g,
    const float* __restrict__ bias,
    const float* __restrict__ F)
{
    constexpr int KT = K / BK;
    extern __shared__ __align__(16) bf16 smembuf[];
#define AS_(st,p,r,c) smembuf[((st) * STAGE_HALVES) + ((p) * BM + (r)) * SPAD + (c)]
#define BS_(st,p,r,c) smembuf[((st) * STAGE_HALVES) + (3 * BM * SPAD) + ((p) * BN + (r)) * SPAD + (c)]

    const int tid  = threadIdx.x;
    const int lane = tid & 31;
    const int wid  = tid >> 5;
    const int gq   = lane >> 2;
    const int t    = lane & 3;
    const int mW   = (wid & 1) * 64;    // warp M offset
    const int nW   = (wid >> 1) * 16;   // warp N offset

    const size_t mBase = (size_t)blockIdx.y * BM;
    const int    nBase = blockIdx.x * BN;

    const bf16* Ap[3] = { A0g + mBase * K, A1g + mBase * K, A2g + mBase * K };
    const bf16* Bp[3] = { B0g + (size_t)nBase * K, B1g + (size_t)nBase * K,
                          B2g + (size_t)nBase * K };

    // register accumulators (pairs along n)
    ull accA2[4][2][2], accC2[4][2][2];
#pragma unroll
    for (int mt = 0; mt < 4; mt++)
#pragma unroll
        for (int nt = 0; nt < 2; nt++) {
            accA2[mt][nt][0] = 0; accA2[mt][nt][1] = 0;
            accC2[mt][nt][0] = 0; accC2[mt][nt][1] = 0;
        }

    auto load_stage = [&](int kt, int st) {
        // A: 3 planes * 128 rows * 2 chunks = 768 slots
#pragma unroll
        for (int u = 0; u < 3; u++) {
            int l = tid + u * 256;
            int p = l >> 8, rr = (l & 255) >> 1, h = l & 1;
            cp16(&AS_(st, p, rr, h * 8), Ap[p] + (size_t)rr * K + kt * BK + h * 8);
        }
        // B: 3 planes * 64 rows * 2 chunks = 384 slots
#pragma unroll
        for (int u = 0; u < 2; u++) {
            int l = tid + u * 256;
            if (l < 384) {
                int p = l / 128, rr = (l & 127) >> 1, h = l & 1;
                cp16(&BS_(st, p, rr, h * 8), Bp[p] + (size_t)rr * K + kt * BK + h * 8);
            }
        }
    };

    load_stage(0, 0);
    CP_COMMIT();
    CP_WAIT0();
    __syncthreads();

    for (int kt = 0; kt < KT; kt++) {
        const int st = kt & 1;
        if (kt + 1 < KT) { load_stage(kt + 1, st ^ 1); CP_COMMIT(); }

        // B fragments: all 3 planes (12 regs)
        uint32_t bfr[3][2][2];
#pragma unroll
        for (int p = 0; p < 3; p++)
#pragma unroll
            for (int nt = 0; nt < 2; nt++) {
                int r = nW + nt * 8 + gq;
                bfr[p][nt][0] = *(const uint32_t*)&BS_(st, p, r, 2 * t);
                bfr[p][nt][1] = *(const uint32_t*)&BS_(st, p, r, 2 * t + 8);
            }
        // A hi fragments (16 regs, persist through chunk)
        uint32_t afrH[4][4];
#pragma unroll
        for (int mt = 0; mt < 4; mt++) {
            int r = mW + mt * 16;
            afrH[mt][0] = *(const uint32_t*)&AS_(st, 0, r + gq, 2 * t);
            afrH[mt][1] = *(const uint32_t*)&AS_(st, 0, r + gq + 8, 2 * t);
            afrH[mt][2] = *(const uint32_t*)&AS_(st, 0, r + gq, 2 * t + 8);
            afrH[mt][3] = *(const uint32_t*)&AS_(st, 0, r + gq + 8, 2 * t + 8);
        }

        float corrD[4][2][4];

        // phase H: hh (zero-C, extract) + hm, hl into corr chain
#pragma unroll
        for (int mt = 0; mt < 4; mt++)
#pragma unroll
            for (int nt = 0; nt < 2; nt++) {
                float d[4] = {0.f, 0.f, 0.f, 0.f};
                mma16816(d, afrH[mt], bfr[0][nt]);          // hh
                fadd2(accA2[mt][nt][0], pack2(d[0], d[1]));
                fadd2(accA2[mt][nt][1], pack2(d[2], d[3]));
                corrD[mt][nt][0] = 0.f; corrD[mt][nt][1] = 0.f;
                corrD[mt][nt][2] = 0.f; corrD[mt][nt][3] = 0.f;
                mma16816(corrD[mt][nt], afrH[mt], bfr[1][nt]);  // hm
                mma16816(corrD[mt][nt], afrH[mt], bfr[2][nt]);  // hl
            }

        // phase M: mh, mm
        {
            uint32_t afrX[4][4];
#pragma unroll
            for (int mt = 0; mt < 4; mt++) {
                int r = mW + mt * 16;
                afrX[mt][0] = *(const uint32_t*)&AS_(st, 1, r + gq, 2 * t);
                afrX[mt][1] = *(const uint32_t*)&AS_(st, 1, r + gq + 8, 2 * t);
                afrX[mt][2] = *(const uint32_t*)&AS_(st, 1, r + gq, 2 * t + 8);
                afrX[mt][3] = *(const uint32_t*)&AS_(st, 1, r + gq + 8, 2 * t + 8);
            }
#pragma unroll
            for (int mt = 0; mt < 4; mt++)
#pragma unroll
                for (int nt = 0; nt < 2; nt++) {
                    mma16816(corrD[mt][nt], afrX[mt], bfr[0][nt]);  // mh
                    mma16816(corrD[mt][nt], afrX[mt], bfr[1][nt]);  // mm
                }
        }
        // phase L: lh, then extract corr
        {
            uint32_t afrX[4][4];
#pragma unroll
            for (int mt = 0; mt < 4; mt++) {
                int r = mW + mt * 16;
                afrX[mt][0] = *(const uint32_t*)&AS_(st, 2, r + gq, 2 * t);
                afrX[mt][1] = *(const uint32_t*)&AS_(st, 2, r + gq + 8, 2 * t);
                afrX[mt][2] = *(const uint32_t*)&AS_(st, 2, r + gq, 2 * t + 8);
                afrX[mt][3] = *(const uint32_t*)&AS_(st, 2, r + gq + 8, 2 * t + 8);
            }
#pragma unroll
            for (int mt = 0; mt < 4; mt++)
#pragma unroll
                for (int nt = 0; nt < 2; nt++) {
                    mma16816(corrD[mt][nt], afrX[mt], bfr[0][nt]);  // lh
                    fadd2(accC2[mt][nt][0], pack2(corrD[mt][nt][0], corrD[mt][nt][1]));
                    fadd2(accC2[mt][nt][1], pack2(corrD[mt][nt][2], corrD[mt][nt][3]));
                }
        }

        if (kt + 1 < KT) { CP_WAIT0(); }
        __syncthreads();
    }

    // epilogue
#pragma unroll
    for (int mt = 0; mt < 4; mt++) {
#pragma unroll
        for (int nt = 0; nt < 2; nt++) {
            size_t r0 = mBase + mW + mt * 16 + gq;
            size_t r1 = r0 + 8;
            int c = nBase + nW + nt * 8 + 2 * t;
            float a00, a01, a10, a11, c00, c01, c10, c11;
            unpack2(accA2[mt][nt][0], a00, a01);
            unpack2(accA2[mt][nt][1], a10, a11);
            unpack2(accC2[mt][nt][0], c00, c01);
            unpack2(accC2[mt][nt][1], c10, c11);
            float b0 = __ldg(bias + c), b1 = __ldg(bias + c + 1);
            float x00 = (a00 + c00) + b0, x01 = (a01 + c01) + b1;
            float x10 = (a10 + c10) + b0, x11 = (a11 + c11) + b1;
            if (EPI == 0) {
                float hv[4] = { fmaxf(x00, 0.f), fmaxf(x01, 0.f),
                                fmaxf(x10, 0.f), fmaxf(x11, 0.f) };
                bf16 h[4], m[4], l[4];
#pragma unroll
                for (int q = 0; q < 4; q++) split3(hv[q], h[q], m[q], l[q]);
                *(__nv_bfloat162*)(g_H0 + r0 * N + c) = __nv_bfloat162(h[0], h[1]);
                *(__nv_bfloat162*)(g_H0 + r1 * N + c) = __nv_bfloat162(h[2], h[3]);
                *(__nv_bfloat162*)(g_H1 + r0 * N + c) = __nv_bfloat162(m[0], m[1]);
                *(__nv_bfloat162*)(g_H1 + r1 * N + c) = __nv_bfloat162(m[2], m[3]);
                *(__nv_bfloat162*)(g_H2 + r0 * N + c) = __nv_bfloat162(l[0], l[1]);
                *(__nv_bfloat162*)(g_H2 + r1 * N + c) = __nv_bfloat162(l[2], l[3]);
            } else {
                float2 f0 = *(const float2*)(F + r0 * N + c);
                float2 f1 = *(const float2*)(F + r1 * N + c);
                float g00 = f0.x * sigmoidf_(x00), g01 = f0.y * sigmoidf_(x01);
                float g10 = f1.x * sigmoidf_(x10), g11 = f1.y * sigmoidf_(x11);
                float2 o0, o1;
                o0.x = (g00 > 0.3f) ? 0.f : g00;  o0.y = (g01 > 0.3f) ? 0.f : g01;
                o1.x = (g10 > 0.3f) ? 0.f : g10;  o1.y = (g11 > 0.3f) ? 0.f : g11;
                *(float2*)(g_comp + r0 * N + c) = o0;
                *(float2*)(g_comp + r1 * N + c) = o1;
            }
        }
    }
#undef AS_
#undef BS_
}

// ---------------- row-wise post-processing (R8 version) ---------------------
#define R3 8

__global__ __launch_bounds__(256) void rowpost_k(
    const float* __restrict__ w_r1, const float* __restrict__ b_r1,
    const float* __restrict__ w_r2, const float* __restrict__ b_r2,
    const float* __restrict__ w_m1, const float* __restrict__ b_m1,
    const float* __restrict__ w_m2, const float* __restrict__ b_m2,
    float* __restrict__ out)
{
    const int tid  = threadIdx.x;
    const int lane = tid & 31;
    const int wid  = tid >> 5;

    __shared__ float sA[8], sB[8], sC[8], sD[8];

    float wr2[16][4];
#pragma unroll
    for (int k = 0; k < 16; k++)
#pragma unroll
        for (int j = 0; j < 4; j++)
            wr2[k][j] = __ldg(w_r2 + k * DIM + tid + 256 * j);
    float br2r[4];
#pragma unroll
    for (int j = 0; j < 4; j++) br2r[j] = __ldg(b_r2 + tid + 256 * j);

    for (int rr = 0; rr < R3; rr++) {
        size_t row = (size_t)blockIdx.x * R3 + rr;
        const float* cr = g_comp + row * DIM;

        __syncthreads();

        float v[4];
#pragma unroll
        for (int j = 0; j < 4; j++) v[j] = cr[tid + 256 * j];

        float cnt = 0.0f;
#pragma unroll
        for (int j = 0; j < 4; j++) cnt += (fabsf(v[j]) < 0.1f) ? 1.0f : 0.0f;
#pragma unroll
        for (int o = 16; o; o >>= 1) cnt += __shfl_xor_sync(0xffffffffu, cnt, o);
        if (lane == 0) sD[wid] = cnt;
        __syncthreads();
        cnt = 0.0f;
#pragma unroll
        for (int w = 0; w < 8; w++) cnt += sD[w];
        float cur_sp = cnt * (1.0f / 1024.0f);

        float hr[16];
#pragma unroll
        for (int k = 0; k < 16; k++) {
            float x = fmaf(cur_sp, __ldg(w_r1 + k),
                      fmaf(0.1f, __ldg(w_r1 + 16 + k), __ldg(b_r1 + k)));
            hr[k] = fmaxf(x, 0.0f);
        }

        float dyn[4];
        float s1 = 0.0f, s2 = 0.0f, mx = -INFINITY;
#pragma unroll
        for (int j = 0; j < 4; j++) {
            float a = br2r[j];
#pragma unroll
            for (int k = 0; k < 16; k++) a = fmaf(hr[k], wr2[k][j], a);
            float rw = sigmoidf_(a);
            float d  = v[j] * rw;
            dyn[j] = d;
            s1 += d;
            s2 = fmaf(d, d, s2);
            mx = fmaxf(mx, d);
        }
#pragma unroll
        for (int o = 16; o; o >>= 1) {
            s1 += __shfl_xor_sync(0xffffffffu, s1, o);
            s2 += __shfl_xor_sync(0xffffffffu, s2, o);
            mx = fmaxf(mx, __shfl_xor_sync(0xffffffffu, mx, o));
        }
        if (lane == 0) { sA[wid] = s1; sB[wid] = s2; sC[wid] = mx; }
        __syncthreads();
        s1 = 0.0f; s2 = 0.0f; mx = -INFINITY;
#pragma unroll
        for (int w = 0; w < 8; w++) {
            s1 += sA[w]; s2 += sB[w]; mx = fmaxf(mx, sC[w]);
        }

        float fmean = s1 * (1.0f / 1024.0f);
        float var   = (s2 - s1 * fmean) * (1.0f / 1023.0f);   // ddof=1
        var = fmaxf(var, 0.0f);
        float fstd = sqrtf(var);

        float a2 = __ldg(b_m2);
#pragma unroll
        for (int k = 0; k < 16; k++) {
            float x = fmaf(fmean, __ldg(w_m1 + k),
                      fmaf(fstd, __ldg(w_m1 + 16 + k),
                      fmaf(mx,   __ldg(w_m1 + 32 + k), __ldg(b_m1 + k))));
            a2 = fmaf(fmaxf(x, 0.0f), __ldg(w_m2 + k), a2);
        }
        float thr = sigmoidf_(a2);

        float* orow = out + row * DIM;
#pragma unroll
        for (int j = 0; j < 4; j++)
            orow[tid + 256 * j] = (fabsf(dyn[j]) > thr) ? dyn[j] : 0.0f;
    }
}

// ---------------- launch -----------------------------------------------------
extern "C" void kernel_launch(void* const* d_in, const int* in_sizes, int n_in,
                              void* d_out, int out_size)
{
    const float* F   = (const float*)d_in[0];
    const float* wg1 = (const float*)d_in[1];
    const float* bg1 = (const float*)d_in[2];
    const float* wg2 = (const float*)d_in[3];
    const float* bg2 = (const float*)d_in[4];
    // d_in[5..8] = competition weights: dead code (win == False always)
    const float* wr1 = (const float*)d_in[9];
    const float* br1 = (const float*)d_in[10];
    const float* wr2 = (const float*)d_in[11];
    const float* br2 = (const float*)d_in[12];
    const float* wm1 = (const float*)d_in[13];
    const float* bm1 = (const float*)d_in[14];
    const float* wm2 = (const float*)d_in[15];
    const float* bm2 = (const float*)d_in[16];
    float* out = (float*)d_out;
    (void)in_sizes; (void)n_in; (void)out_size;

    bf16 *W10, *W11, *W12, *W20, *W21, *W22, *F0, *F1, *F2, *H0, *H1, *H2;
    cudaGetSymbolAddress((void**)&W10, g_W10);
    cudaGetSymbolAddress((void**)&W11, g_W11);
    cudaGetSymbolAddress((void**)&W12, g_W12);
    cudaGetSymbolAddress((void**)&W20, g_W20);
    cudaGetSymbolAddress((void**)&W21, g_W21);
    cudaGetSymbolAddress((void**)&W22, g_W22);
    cudaGetSymbolAddress((void**)&F0, g_F0);
    cudaGetSymbolAddress((void**)&F1, g_F1);
    cudaGetSymbolAddress((void**)&F2, g_F2);
    cudaGetSymbolAddress((void**)&H0, g_H0);
    cudaGetSymbolAddress((void**)&H1, g_H1);
    cudaGetSymbolAddress((void**)&H2, g_H2);

    static int attr_done = 0;
    if (!attr_done) {
        cudaFuncSetAttribute(gemm_tc<0, DIM, HID>,
                             cudaFuncAttributeMaxDynamicSharedMemorySize, SMEM_BYTES);
        cudaFuncSetAttribute(gemm_tc<1, HID, DIM>,
                             cudaFuncAttributeMaxDynamicSharedMemorySize, SMEM_BYTES);
        attr_done = 1;
    }

    cvt_w_k<<<(DIM * HID + 255) / 256, 256>>>(wg1, W10, W11, W12, DIM, HID);
    cvt_w_k<<<(HID * DIM + 255) / 256, 256>>>(wg2, W20, W21, W22, HID, DIM);
    cvt_f_k<<<(BATCH * DIM / 4) / 256, 256>>>(F);

    // GEMM1: H = relu(F @ Wg1 + bg1)
    gemm_tc<0, DIM, HID><<<dim3(HID / BN, BATCH / BM), 256, SMEM_BYTES>>>(
        F0, F1, F2, W10, W11, W12, bg1, nullptr);
    // GEMM2: comp = thresh(F * sigmoid(H @ Wg2 + bg2))
    gemm_tc<1, HID, DIM><<<dim3(DIM / BN, BATCH / BM), 256, SMEM_BYTES>>>(
        H0, H1, H2, W20, W21, W22, bg2, F);
    // row-wise post-processing
    rowpost_k<<<BATCH / R3, 256>>>(wr1, br1, wr2, br2, wm1, bm1, wm2, bm2, out);
}

// round 10
// speedup vs baseline: 1.2600x; 1.2600x over previous
#include <cuda_runtime.h>
#include <cuda_bf16.h>
#include <cstdint>
#include <math.h>

#define BATCH 32768
#define DIM   1024
#define HID   256

typedef __nv_bfloat16 bf16;
typedef unsigned long long ull;

// ---------------- device scratch (no runtime allocation) -------------------
__device__ bf16 g_F0[(size_t)BATCH * DIM];
__device__ bf16 g_F1[(size_t)BATCH * DIM];
__device__ bf16 g_F2[(size_t)BATCH * DIM];
__device__ bf16 g_H0[(size_t)BATCH * HID];
__device__ bf16 g_H1[(size_t)BATCH * HID];
__device__ bf16 g_H2[(size_t)BATCH * HID];
__device__ bf16 g_W10[DIM * HID], g_W11[DIM * HID], g_W12[DIM * HID]; // [N=256][K=1024]
__device__ bf16 g_W20[HID * DIM], g_W21[HID * DIM], g_W22[HID * DIM]; // [N=1024][K=256]
__device__ float g_comp[(size_t)BATCH * DIM];  // 128 MB

__device__ __forceinline__ float sigmoidf_(float x) {
    return 1.0f / (1.0f + expf(-x));
}

__device__ __forceinline__ void split3(float x, bf16& h, bf16& m, bf16& l) {
    h = __float2bfloat16_rn(x);
    float r1 = x - __bfloat162float(h);     // exact in fp32
    m = __float2bfloat16_rn(r1);
    float r2 = r1 - __bfloat162float(m);    // exact in fp32
    l = __float2bfloat16_rn(r2);
}

__device__ __forceinline__ void cp16(void* s, const void* gp) {
    uint32_t sa = (uint32_t)__cvta_generic_to_shared(s);
    asm volatile("cp.async.cg.shared.global [%0], [%1], 16;\n" :: "r"(sa), "l"(gp));
}
#define CP_COMMIT() asm volatile("cp.async.commit_group;\n")
#define CP_WAIT1()  asm volatile("cp.async.wait_group 1;\n")
#define CP_WAIT0()  asm volatile("cp.async.wait_group 0;\n")

__device__ __forceinline__ void mma16816(float* d, const uint32_t* a, const uint32_t* b) {
    asm volatile(
        "mma.sync.aligned.m16n8k16.row.col.f32.bf16.bf16.f32 "
        "{%0,%1,%2,%3}, {%4,%5,%6,%7}, {%8,%9}, {%0,%1,%2,%3};\n"
        : "+f"(d[0]), "+f"(d[1]), "+f"(d[2]), "+f"(d[3])
        : "r"(a[0]), "r"(a[1]), "r"(a[2]), "r"(a[3]), "r"(b[0]), "r"(b[1]));
}

// IEEE-rn packed fp32 add (two independent scalar rn-adds)
__device__ __forceinline__ void fadd2(ull& d, ull a) {
    asm("add.rn.f32x2 %0, %0, %1;" : "+l"(d) : "l"(a));
}
__device__ __forceinline__ ull pack2(float lo, float hi) {
    ull r;
    asm("mov.b64 %0, {%1, %2};" : "=l"(r) : "f"(lo), "f"(hi));
    return r;
}
__device__ __forceinline__ void unpack2(ull v, float& lo, float& hi) {
    asm("mov.b64 {%0, %1}, %2;" : "=f"(lo), "=f"(hi) : "l"(v));
}

// ---------------- conversion kernels ---------------------------------------
__global__ __launch_bounds__(256) void cvt_f_k(const float* __restrict__ x) {
    size_t i = ((size_t)blockIdx.x * 256 + threadIdx.x) * 4;
    float4 v = *(const float4*)(x + i);
    bf16 h[4], m[4], l[4];
    split3(v.x, h[0], m[0], l[0]);
    split3(v.y, h[1], m[1], l[1]);
    split3(v.z, h[2], m[2], l[2]);
    split3(v.w, h[3], m[3], l[3]);
    *(__nv_bfloat162*)(g_F0 + i)     = __nv_bfloat162(h[0], h[1]);
    *(__nv_bfloat162*)(g_F0 + i + 2) = __nv_bfloat162(h[2], h[3]);
    *(__nv_bfloat162*)(g_F1 + i)     = __nv_bfloat162(m[0], m[1]);
    *(__nv_bfloat162*)(g_F1 + i + 2) = __nv_bfloat162(m[2], m[3]);
    *(__nv_bfloat162*)(g_F2 + i)     = __nv_bfloat162(l[0], l[1]);
    *(__nv_bfloat162*)(g_F2 + i + 2) = __nv_bfloat162(l[2], l[3]);
}

__global__ __launch_bounds__(256) void cvt_w_k(const float* __restrict__ w,
                                               bf16* __restrict__ w0,
                                               bf16* __restrict__ w1,
                                               bf16* __restrict__ w2,
                                               int K, int N) {
    int i = blockIdx.x * 256 + threadIdx.x;
    if (i >= K * N) return;
    int k = i / N, n = i % N;
    bf16 h, m, l;
    split3(w[i], h, m, l);
    w0[(size_t)n * K + k] = h;
    w1[(size_t)n * K + k] = m;
    w2[(size_t)n * K + k] = l;
}

// ---------------- tensor-core GEMM, register accumulation -------------------
// Per 16-k chunk: hh via zero-C MMA -> acc (fp32-rn), 5 corr terms
// (hm,hl,mh,mm,lh) D-chained within chunk only, extracted -> same acc.
// Cross-chunk sums are clean fp32-rn chains (R9: rel_err 1.56e-6, PASS).
// R10: regs<128 (2 CTA/SM), 3-stage cp.async pipeline, 1 sync/chunk.
#define BM 128
#define BN 64
#define BK 16
#define SPAD 24
#define NSTAGE 3
#define STAGE_HALVES (3 * (BM + BN) * SPAD)          // 13824 bf16 per stage
#define SMEM_BYTES   (NSTAGE * STAGE_HALVES * 2)     // 82944 B

template <int EPI, int K, int N>
__global__ __launch_bounds__(256, 2) void gemm_tc(
    const bf16* __restrict__ A0g, const bf16* __restrict__ A1g, const bf16* __restrict__ A2g,
    const bf16* __restrict__ B0g, const bf16* __restrict__ B1g, const bf16* __restrict__ B2g,
    const float* __restrict__ bias,
    const float* __restrict__ F)
{
    constexpr int KT = K / BK;
    extern __shared__ __align__(16) bf16 smembuf[];
#define AS_(st,p,r,c) smembuf[((st) * STAGE_HALVES) + ((p) * BM + (r)) * SPAD + (c)]
#define BS_(st,p,r,c) smembuf[((st) * STAGE_HALVES) + (3 * BM * SPAD) + ((p) * BN + (r)) * SPAD + (c)]

    const int tid  = threadIdx.x;
    const int lane = tid & 31;
    const int wid  = tid >> 5;
    const int gq   = lane >> 2;
    const int t    = lane & 3;
    const int mW   = (wid & 1) * 64;    // warp M offset
    const int nW   = (wid >> 1) * 16;   // warp N offset

    const size_t mBase = (size_t)blockIdx.y * BM;
    const int    nBase = blockIdx.x * BN;

    const bf16* Ap[3] = { A0g + mBase * K, A1g + mBase * K, A2g + mBase * K };
    const bf16* Bp[3] = { B0g + (size_t)nBase * K, B1g + (size_t)nBase * K,
                          B2g + (size_t)nBase * K };

    // single register accumulator (pairs along n): acc[mt][nt][pair]
    ull acc2[4][2][2];
#pragma unroll
    for (int mt = 0; mt < 4; mt++)
#pragma unroll
        for (int nt = 0; nt < 2; nt++) {
            acc2[mt][nt][0] = 0; acc2[mt][nt][1] = 0;
        }

    auto load_stage = [&](int kt, int st) {
#pragma unroll
        for (int u = 0; u < 3; u++) {
            int l = tid + u * 256;
            int p = l >> 8, rr = (l & 255) >> 1, h = l & 1;
            cp16(&AS_(st, p, rr, h * 8), Ap[p] + (size_t)rr * K + kt * BK + h * 8);
        }
#pragma unroll
        for (int u = 0; u < 2; u++) {
            int l = tid + u * 256;
            if (l < 384) {
                int p = l / 128, rr = (l & 127) >> 1, h = l & 1;
                cp16(&BS_(st, p, rr, h * 8), Bp[p] + (size_t)rr * K + kt * BK + h * 8);
            }
        }
    };

    // prologue: stages 0 and 1 in flight
    load_stage(0, 0);
    CP_COMMIT();
    if (KT > 1) { load_stage(1, 1); CP_COMMIT(); }
    CP_WAIT1();               // stage 0 arrived
    __syncthreads();

    for (int kt = 0; kt < KT; kt++) {
        const int st = kt % NSTAGE;
        // issue loads for kt+2 into stage (kt+2)%3 == (kt-1)%3 (safe: the
        // barrier at the end of iter kt-1 proved all warps finished reading it)
        if (kt + 2 < KT) { load_stage(kt + 2, (kt + 2) % NSTAGE); CP_COMMIT(); }

        // B fragments: all 3 planes (12 regs)
        uint32_t bfr[3][2][2];
#pragma unroll
        for (int p = 0; p < 3; p++)
#pragma unroll
            for (int nt = 0; nt < 2; nt++) {
                int r = nW + nt * 8 + gq;
                bfr[p][nt][0] = *(const uint32_t*)&BS_(st, p, r, 2 * t);
                bfr[p][nt][1] = *(const uint32_t*)&BS_(st, p, r, 2 * t + 8);
            }

#pragma unroll
        for (int mt = 0; mt < 4; mt++) {
            // A fragments for all 3 planes of this mt (12 regs)
            uint32_t afr[3][4];
#pragma unroll
            for (int p = 0; p < 3; p++) {
                int r = mW + mt * 16;
                afr[p][0] = *(const uint32_t*)&AS_(st, p, r + gq, 2 * t);
                afr[p][1] = *(const uint32_t*)&AS_(st, p, r + gq + 8, 2 * t);
                afr[p][2] = *(const uint32_t*)&AS_(st, p, r + gq, 2 * t + 8);
                afr[p][3] = *(const uint32_t*)&AS_(st, p, r + gq + 8, 2 * t + 8);
            }
#pragma unroll
            for (int nt = 0; nt < 2; nt++) {
                float d[4] = {0.f, 0.f, 0.f, 0.f};
                mma16816(d, afr[0], bfr[0][nt]);              // hh
                fadd2(acc2[mt][nt][0], pack2(d[0], d[1]));
                fadd2(acc2[mt][nt][1], pack2(d[2], d[3]));
                float c[4] = {0.f, 0.f, 0.f, 0.f};
                mma16816(c, afr[0], bfr[1][nt]);              // hm
                mma16816(c, afr[0], bfr[2][nt]);              // hl
                mma16816(c, afr[1], bfr[0][nt]);              // mh
                mma16816(c, afr[1], bfr[1][nt]);              // mm
                mma16816(c, afr[2], bfr[0][nt]);              // lh
                fadd2(acc2[mt][nt][0], pack2(c[0], c[1]));
                fadd2(acc2[mt][nt][1], pack2(c[2], c[3]));
            }
        }

        if (kt + 1 < KT) {
            if (kt + 2 < KT) CP_WAIT1();   // stage kt+1 arrived (kt+2 may fly)
            else             CP_WAIT0();   // last stage: drain everything
            __syncthreads();               // one barrier per chunk
        }
    }

    // epilogue
#pragma unroll
    for (int mt = 0; mt < 4; mt++) {
#pragma unroll
        for (int nt = 0; nt < 2; nt++) {
            size_t r0 = mBase + mW + mt * 16 + gq;
            size_t r1 = r0 + 8;
            int c = nBase + nW + nt * 8 + 2 * t;
            float a00, a01, a10, a11;
            unpack2(acc2[mt][nt][0], a00, a01);
            unpack2(acc2[mt][nt][1], a10, a11);
            float b0 = __ldg(bias + c), b1 = __ldg(bias + c + 1);
            float x00 = a00 + b0, x01 = a01 + b1;
            float x10 = a10 + b0, x11 = a11 + b1;
            if (EPI == 0) {
                float hv[4] = { fmaxf(x00, 0.f), fmaxf(x01, 0.f),
                                fmaxf(x10, 0.f), fmaxf(x11, 0.f) };
                bf16 h[4], m[4], l[4];
#pragma unroll
                for (int q = 0; q < 4; q++) split3(hv[q], h[q], m[q], l[q]);
                *(__nv_bfloat162*)(g_H0 + r0 * N + c) = __nv_bfloat162(h[0], h[1]);
                *(__nv_bfloat162*)(g_H0 + r1 * N + c) = __nv_bfloat162(h[2], h[3]);
                *(__nv_bfloat162*)(g_H1 + r0 * N + c) = __nv_bfloat162(m[0], m[1]);
                *(__nv_bfloat162*)(g_H1 + r1 * N + c) = __nv_bfloat162(m[2], m[3]);
                *(__nv_bfloat162*)(g_H2 + r0 * N + c) = __nv_bfloat162(l[0], l[1]);
                *(__nv_bfloat162*)(g_H2 + r1 * N + c) = __nv_bfloat162(l[2], l[3]);
            } else {
                float2 f0 = *(const float2*)(F + r0 * N + c);
                float2 f1 = *(const float2*)(F + r1 * N + c);
                float g00 = f0.x * sigmoidf_(x00), g01 = f0.y * sigmoidf_(x01);
                float g10 = f1.x * sigmoidf_(x10), g11 = f1.y * sigmoidf_(x11);
                float2 o0, o1;
                o0.x = (g00 > 0.3f) ? 0.f : g00;  o0.y = (g01 > 0.3f) ? 0.f : g01;
                o1.x = (g10 > 0.3f) ? 0.f : g10;  o1.y = (g11 > 0.3f) ? 0.f : g11;
                *(float2*)(g_comp + r0 * N + c) = o0;
                *(float2*)(g_comp + r1 * N + c) = o1;
            }
        }
    }
#undef AS_
#undef BS_
}

// ---------------- row-wise post-processing ----------------------------------
#define R3 8

__global__ __launch_bounds__(256) void rowpost_k(
    const float* __restrict__ w_r1, const float* __restrict__ b_r1,
    const float* __restrict__ w_r2, const float* __restrict__ b_r2,
    const float* __restrict__ w_m1, const float* __restrict__ b_m1,
    const float* __restrict__ w_m2, const float* __restrict__ b_m2,
    float* __restrict__ out)
{
    const int tid  = threadIdx.x;
    const int lane = tid & 31;
    const int wid  = tid >> 5;

    __shared__ float sA[8], sB[8], sC[8], sD[8];

    float wr2[16][4];
#pragma unroll
    for (int k = 0; k < 16; k++)
#pragma unroll
        for (int j = 0; j < 4; j++)
            wr2[k][j] = __ldg(w_r2 + k * DIM + tid + 256 * j);
    float br2r[4];
#pragma unroll
    for (int j = 0; j < 4; j++) br2r[j] = __ldg(b_r2 + tid + 256 * j);

    for (int rr = 0; rr < R3; rr++) {
        size_t row = (size_t)blockIdx.x * R3 + rr;
        const float* cr = g_comp + row * DIM;

        __syncthreads();

        float v[4];
#pragma unroll
        for (int j = 0; j < 4; j++) v[j] = cr[tid + 256 * j];

        float cnt = 0.0f;
#pragma unroll
        for (int j = 0; j < 4; j++) cnt += (fabsf(v[j]) < 0.1f) ? 1.0f : 0.0f;
#pragma unroll
        for (int o = 16; o; o >>= 1) cnt += __shfl_xor_sync(0xffffffffu, cnt, o);
        if (lane == 0) sD[wid] = cnt;
        __syncthreads();
        cnt = 0.0f;
#pragma unroll
        for (int w = 0; w < 8; w++) cnt += sD[w];
        float cur_sp = cnt * (1.0f / 1024.0f);

        float hr[16];
#pragma unroll
        for (int k = 0; k < 16; k++) {
            float x = fmaf(cur_sp, __ldg(w_r1 + k),
                      fmaf(0.1f, __ldg(w_r1 + 16 + k), __ldg(b_r1 + k)));
            hr[k] = fmaxf(x, 0.0f);
        }

        float dyn[4];
        float s1 = 0.0f, s2 = 0.0f, mx = -INFINITY;
#pragma unroll
        for (int j = 0; j < 4; j++) {
            float a = br2r[j];
#pragma unroll
            for (int k = 0; k < 16; k++) a = fmaf(hr[k], wr2[k][j], a);
            float rw = sigmoidf_(a);
            float d  = v[j] * rw;
            dyn[j] = d;
            s1 += d;
            s2 = fmaf(d, d, s2);
            mx = fmaxf(mx, d);
        }
#pragma unroll
        for (int o = 16; o; o >>= 1) {
            s1 += __shfl_xor_sync(0xffffffffu, s1, o);
            s2 += __shfl_xor_sync(0xffffffffu, s2, o);
            mx = fmaxf(mx, __shfl_xor_sync(0xffffffffu, mx, o));
        }
        if (lane == 0) { sA[wid] = s1; sB[wid] = s2; sC[wid] = mx; }
        __syncthreads();
        s1 = 0.0f; s2 = 0.0f; mx = -INFINITY;
#pragma unroll
        for (int w = 0; w < 8; w++) {
            s1 += sA[w]; s2 += sB[w]; mx = fmaxf(mx, sC[w]);
        }

        float fmean = s1 * (1.0f / 1024.0f);
        float var   = (s2 - s1 * fmean) * (1.0f / 1023.0f);   // ddof=1
        var = fmaxf(var, 0.0f);
        float fstd = sqrtf(var);

        float a2 = __ldg(b_m2);
#pragma unroll
        for (int k = 0; k < 16; k++) {
            float x = fmaf(fmean, __ldg(w_m1 + k),
                      fmaf(fstd, __ldg(w_m1 + 16 + k),
                      fmaf(mx,   __ldg(w_m1 + 32 + k), __ldg(b_m1 + k))));
            a2 = fmaf(fmaxf(x, 0.0f), __ldg(w_m2 + k), a2);
        }
        float thr = sigmoidf_(a2);

        float* orow = out + row * DIM;
#pragma unroll
        for (int j = 0; j < 4; j++)
            orow[tid + 256 * j] = (fabsf(dyn[j]) > thr) ? dyn[j] : 0.0f;
    }
}

// ---------------- launch -----------------------------------------------------
extern "C" void kernel_launch(void* const* d_in, const int* in_sizes, int n_in,
                              void* d_out, int out_size)
{
    const float* F   = (const float*)d_in[0];
    const float* wg1 = (const float*)d_in[1];
    const float* bg1 = (const float*)d_in[2];
    const float* wg2 = (const float*)d_in[3];
    const float* bg2 = (const float*)d_in[4];
    // d_in[5..8] = competition weights: dead code (win == False always)
    const float* wr1 = (const float*)d_in[9];
    const float* br1 = (const float*)d_in[10];
    const float* wr2 = (const float*)d_in[11];
    const float* br2 = (const float*)d_in[12];
    const float* wm1 = (const float*)d_in[13];
    const float* bm1 = (const float*)d_in[14];
    const float* wm2 = (const float*)d_in[15];
    const float* bm2 = (const float*)d_in[16];
    float* out = (float*)d_out;
    (void)in_sizes; (void)n_in; (void)out_size;

    bf16 *W10, *W11, *W12, *W20, *W21, *W22, *F0, *F1, *F2, *H0, *H1, *H2;
    cudaGetSymbolAddress((void**)&W10, g_W10);
    cudaGetSymbolAddress((void**)&W11, g_W11);
    cudaGetSymbolAddress((void**)&W12, g_W12);
    cudaGetSymbolAddress((void**)&W20, g_W20);
    cudaGetSymbolAddress((void**)&W21, g_W21);
    cudaGetSymbolAddress((void**)&W22, g_W22);
    cudaGetSymbolAddress((void**)&F0, g_F0);
    cudaGetSymbolAddress((void**)&F1, g_F1);
    cudaGetSymbolAddress((void**)&F2, g_F2);
    cudaGetSymbolAddress((void**)&H0, g_H0);
    cudaGetSymbolAddress((void**)&H1, g_H1);
    cudaGetSymbolAddress((void**)&H2, g_H2);

    static int attr_done = 0;
    if (!attr_done) {
        cudaFuncSetAttribute(gemm_tc<0, DIM, HID>,
                             cudaFuncAttributeMaxDynamicSharedMemorySize, SMEM_BYTES);
        cudaFuncSetAttribute(gemm_tc<1, HID, DIM>,
                             cudaFuncAttributeMaxDynamicSharedMemorySize, SMEM_BYTES);
        attr_done = 1;
    }

    cvt_w_k<<<(DIM * HID + 255) / 256, 256>>>(wg1, W10, W11, W12, DIM, HID);
    cvt_w_k<<<(HID * DIM + 255) / 256, 256>>>(wg2, W20, W21, W22, HID, DIM);
    cvt_f_k<<<(BATCH * DIM / 4) / 256, 256>>>(F);

    // GEMM1: H = relu(F @ Wg1 + bg1)
    gemm_tc<0, DIM, HID><<<dim3(HID / BN, BATCH / BM), 256, SMEM_BYTES>>>(
        F0, F1, F2, W10, W11, W12, bg1, nullptr);
    // GEMM2: comp = thresh(F * sigmoid(H @ Wg2 + bg2))
    gemm_tc<1, HID, DIM><<<dim3(DIM / BN, BATCH / BM), 256, SMEM_BYTES>>>(
        H0, H1, H2, W20, W21, W22, bg2, F);
    // row-wise post-processing
    rowpost_k<<<BATCH / R3, 256>>>(wr1, br1, wr2, br2, wm1, bm1, wm2, bm2, out);
}

// round 11
// speedup vs baseline: 1.3095x; 1.0392x over previous
#include <cuda_runtime.h>
#include <cuda_bf16.h>
#include <cstdint>
#include <math.h>

#define BATCH 32768
#define DIM   1024
#define HID   256

typedef __nv_bfloat16 bf16;
typedef unsigned long long ull;

// ---------------- device scratch (no runtime allocation) -------------------
__device__ bf16 g_F0[(size_t)BATCH * DIM];
__device__ bf16 g_F1[(size_t)BATCH * DIM];
__device__ bf16 g_F2[(size_t)BATCH * DIM];
__device__ bf16 g_H0[(size_t)BATCH * HID];
__device__ bf16 g_H1[(size_t)BATCH * HID];
__device__ bf16 g_H2[(size_t)BATCH * HID];
__device__ bf16 g_W10[DIM * HID], g_W11[DIM * HID], g_W12[DIM * HID]; // [N=256][K=1024]
__device__ bf16 g_W20[HID * DIM], g_W21[HID * DIM], g_W22[HID * DIM]; // [N=1024][K=256]
__device__ float g_comp[(size_t)BATCH * DIM];  // 128 MB

__device__ __forceinline__ float sigmoidf_(float x) {
    return 1.0f / (1.0f + expf(-x));
}

__device__ __forceinline__ void split3(float x, bf16& h, bf16& m, bf16& l) {
    h = __float2bfloat16_rn(x);
    float r1 = x - __bfloat162float(h);     // exact in fp32
    m = __float2bfloat16_rn(r1);
    float r2 = r1 - __bfloat162float(m);    // exact in fp32
    l = __float2bfloat16_rn(r2);
}

__device__ __forceinline__ void cp16(void* s, const void* gp) {
    uint32_t sa = (uint32_t)__cvta_generic_to_shared(s);
    asm volatile("cp.async.cg.shared.global [%0], [%1], 16;\n" :: "r"(sa), "l"(gp));
}
#define CP_COMMIT() asm volatile("cp.async.commit_group;\n")
#define CP_WAIT1()  asm volatile("cp.async.wait_group 1;\n")
#define CP_WAIT0()  asm volatile("cp.async.wait_group 0;\n")

__device__ __forceinline__ void mma16816(float* d, const uint32_t* a, const uint32_t* b) {
    asm volatile(
        "mma.sync.aligned.m16n8k16.row.col.f32.bf16.bf16.f32 "
        "{%0,%1,%2,%3}, {%4,%5,%6,%7}, {%8,%9}, {%0,%1,%2,%3};\n"
        : "+f"(d[0]), "+f"(d[1]), "+f"(d[2]), "+f"(d[3])
        : "r"(a[0]), "r"(a[1]), "r"(a[2]), "r"(a[3]), "r"(b[0]), "r"(b[1]));
}

// warp-collective 4-matrix ldmatrix (each lane passes its own row address)
__device__ __forceinline__ void ldsm4(uint32_t* r, const void* p) {
    uint32_t a = (uint32_t)__cvta_generic_to_shared(p);
    asm volatile("ldmatrix.sync.aligned.m8n8.x4.shared.b16 {%0,%1,%2,%3}, [%4];"
        : "=r"(r[0]), "=r"(r[1]), "=r"(r[2]), "=r"(r[3]) : "r"(a));
}

// IEEE-rn packed fp32 add (two independent scalar rn-adds)
__device__ __forceinline__ void fadd2(ull& d, ull a) {
    asm("add.rn.f32x2 %0, %0, %1;" : "+l"(d) : "l"(a));
}
__device__ __forceinline__ ull pack2(float lo, float hi) {
    ull r;
    asm("mov.b64 %0, {%1, %2};" : "=l"(r) : "f"(lo), "f"(hi));
    return r;
}
__device__ __forceinline__ void unpack2(ull v, float& lo, float& hi) {
    asm("mov.b64 {%0, %1}, %2;" : "=f"(lo), "=f"(hi) : "l"(v));
}

// ---------------- conversion kernels ---------------------------------------
__global__ __launch_bounds__(256) void cvt_f_k(const float* __restrict__ x) {
    size_t i = ((size_t)blockIdx.x * 256 + threadIdx.x) * 4;
    float4 v = *(const float4*)(x + i);
    bf16 h[4], m[4], l[4];
    split3(v.x, h[0], m[0], l[0]);
    split3(v.y, h[1], m[1], l[1]);
    split3(v.z, h[2], m[2], l[2]);
    split3(v.w, h[3], m[3], l[3]);
    *(__nv_bfloat162*)(g_F0 + i)     = __nv_bfloat162(h[0], h[1]);
    *(__nv_bfloat162*)(g_F0 + i + 2) = __nv_bfloat162(h[2], h[3]);
    *(__nv_bfloat162*)(g_F1 + i)     = __nv_bfloat162(m[0], m[1]);
    *(__nv_bfloat162*)(g_F1 + i + 2) = __nv_bfloat162(m[2], m[3]);
    *(__nv_bfloat162*)(g_F2 + i)     = __nv_bfloat162(l[0], l[1]);
    *(__nv_bfloat162*)(g_F2 + i + 2) = __nv_bfloat162(l[2], l[3]);
}

__global__ __launch_bounds__(256) void cvt_w_k(const float* __restrict__ w,
                                               bf16* __restrict__ w0,
                                               bf16* __restrict__ w1,
                                               bf16* __restrict__ w2,
                                               int K, int N) {
    int i = blockIdx.x * 256 + threadIdx.x;
    if (i >= K * N) return;
    int k = i / N, n = i % N;
    bf16 h, m, l;
    split3(w[i], h, m, l);
    w0[(size_t)n * K + k] = h;
    w1[(size_t)n * K + k] = m;
    w2[(size_t)n * K + k] = l;
}

// ---------------- tensor-core GEMM, register accumulation -------------------
// Per 16-k chunk: hh via zero-C MMA -> acc (fp32-rn fadd2), 5 corr terms
// (hm,hl,mh,mm,lh) D-chained within chunk only, extracted -> same acc.
// Fragment loads via ldmatrix.x4 (15 LDSM/chunk vs 60 LDS.32 in R10).
#define BM 128
#define BN 64
#define BK 16
#define SPAD 24
#define NSTAGE 3
#define STAGE_HALVES (3 * (BM + BN) * SPAD)          // 13824 bf16 per stage
#define SMEM_BYTES   (NSTAGE * STAGE_HALVES * 2)     // 82944 B

template <int EPI, int K, int N>
__global__ __launch_bounds__(256, 2) void gemm_tc(
    const bf16* __restrict__ A0g, const bf16* __restrict__ A1g, const bf16* __restrict__ A2g,
    const bf16* __restrict__ B0g, const bf16* __restrict__ B1g, const bf16* __restrict__ B2g,
    const float* __restrict__ bias,
    const float* __restrict__ F)
{
    constexpr int KT = K / BK;
    extern __shared__ __align__(16) bf16 smembuf[];
#define AS_(st,p,r,c) smembuf[((st) * STAGE_HALVES) + ((p) * BM + (r)) * SPAD + (c)]
#define BS_(st,p,r,c) smembuf[((st) * STAGE_HALVES) + (3 * BM * SPAD) + ((p) * BN + (r)) * SPAD + (c)]

    const int tid  = threadIdx.x;
    const int lane = tid & 31;
    const int wid  = tid >> 5;
    const int gq   = lane >> 2;
    const int t    = lane & 3;
    const int mW   = (wid & 1) * 64;    // warp M offset
    const int nW   = (wid >> 1) * 16;   // warp N offset

    // ldmatrix lane-address components (see fragment layout of m16n8k16):
    //  A x4: mat0 rows0-7/k0-7, mat1 rows8-15/k0-7, mat2 rows0-7/k8-15, mat3 rows8-15/k8-15
    const int aRowL = (lane & 7) + ((lane >> 3) & 1) * 8;   // + mW + mt*16
    const int aColL = (lane >> 4) * 8;
    //  B x4: mat0 nt0/k0-7, mat1 nt0/k8-15, mat2 nt1/k0-7, mat3 nt1/k8-15
    const int bRowL = nW + ((lane >> 4) & 1) * 8 + (lane & 7);
    const int bColL = ((lane >> 3) & 1) * 8;

    const size_t mBase = (size_t)blockIdx.y * BM;
    const int    nBase = blockIdx.x * BN;

    const bf16* Ap[3] = { A0g + mBase * K, A1g + mBase * K, A2g + mBase * K };
    const bf16* Bp[3] = { B0g + (size_t)nBase * K, B1g + (size_t)nBase * K,
                          B2g + (size_t)nBase * K };

    // register accumulator (pairs along n): acc2[mt][nt][pair]
    ull acc2[4][2][2];
#pragma unroll
    for (int mt = 0; mt < 4; mt++)
#pragma unroll
        for (int nt = 0; nt < 2; nt++) {
            acc2[mt][nt][0] = 0; acc2[mt][nt][1] = 0;
        }

    auto load_stage = [&](int kt, int st) {
#pragma unroll
        for (int u = 0; u < 3; u++) {
            int l = tid + u * 256;
            int p = l >> 8, rr = (l & 255) >> 1, h = l & 1;
            cp16(&AS_(st, p, rr, h * 8), Ap[p] + (size_t)rr * K + kt * BK + h * 8);
        }
#pragma unroll
        for (int u = 0; u < 2; u++) {
            int l = tid + u * 256;
            if (l < 384) {
                int p = l / 128, rr = (l & 127) >> 1, h = l & 1;
                cp16(&BS_(st, p, rr, h * 8), Bp[p] + (size_t)rr * K + kt * BK + h * 8);
            }
        }
    };

    // prologue: stages 0 and 1 in flight
    load_stage(0, 0);
    CP_COMMIT();
    if (KT > 1) { load_stage(1, 1); CP_COMMIT(); }
    CP_WAIT1();               // stage 0 arrived
    __syncthreads();

    for (int kt = 0; kt < KT; kt++) {
        const int st = kt % NSTAGE;
        if (kt + 2 < KT) { load_stage(kt + 2, (kt + 2) % NSTAGE); CP_COMMIT(); }

        // B fragments: 3 planes x (both nt) in 3 LDSM.x4
        // reg order: r0=b[nt0][0], r1=b[nt0][1], r2=b[nt1][0], r3=b[nt1][1]
        uint32_t bfr[3][4];
#pragma unroll
        for (int p = 0; p < 3; p++)
            ldsm4(bfr[p], &BS_(st, p, bRowL, bColL));

#pragma unroll
        for (int mt = 0; mt < 4; mt++) {
            // A fragments: 3 planes in 3 LDSM.x4 (reg order == mma a0..a3)
            uint32_t afr[3][4];
#pragma unroll
            for (int p = 0; p < 3; p++)
                ldsm4(afr[p], &AS_(st, p, mW + mt * 16 + aRowL, aColL));
#pragma unroll
            for (int nt = 0; nt < 2; nt++) {
                const uint32_t b0[2] = { bfr[0][nt * 2], bfr[0][nt * 2 + 1] };
                const uint32_t b1[2] = { bfr[1][nt * 2], bfr[1][nt * 2 + 1] };
                const uint32_t b2[2] = { bfr[2][nt * 2], bfr[2][nt * 2 + 1] };
                float d[4] = {0.f, 0.f, 0.f, 0.f};
                mma16816(d, afr[0], b0);               // hh
                fadd2(acc2[mt][nt][0], pack2(d[0], d[1]));
                fadd2(acc2[mt][nt][1], pack2(d[2], d[3]));
                float c[4] = {0.f, 0.f, 0.f, 0.f};
                mma16816(c, afr[0], b1);               // hm
                mma16816(c, afr[0], b2);               // hl
                mma16816(c, afr[1], b0);               // mh
                mma16816(c, afr[1], b1);               // mm
                mma16816(c, afr[2], b0);               // lh
                fadd2(acc2[mt][nt][0], pack2(c[0], c[1]));
                fadd2(acc2[mt][nt][1], pack2(c[2], c[3]));
            }
        }

        if (kt + 1 < KT) {
            if (kt + 2 < KT) CP_WAIT1();   // stage kt+1 arrived (kt+2 may fly)
            else             CP_WAIT0();   // last stage: drain everything
            __syncthreads();               // one barrier per chunk
        }
    }

    // epilogue
#pragma unroll
    for (int mt = 0; mt < 4; mt++) {
#pragma unroll
        for (int nt = 0; nt < 2; nt++) {
            size_t r0 = mBase + mW + mt * 16 + gq;
            size_t r1 = r0 + 8;
            int c = nBase + nW + nt * 8 + 2 * t;
            float a00, a01, a10, a11;
            unpack2(acc2[mt][nt][0], a00, a01);
            unpack2(acc2[mt][nt][1], a10, a11);
            float b0 = __ldg(bias + c), b1 = __ldg(bias + c + 1);
            float x00 = a00 + b0, x01 = a01 + b1;
            float x10 = a10 + b0, x11 = a11 + b1;
            if (EPI == 0) {
                float hv[4] = { fmaxf(x00, 0.f), fmaxf(x01, 0.f),
                                fmaxf(x10, 0.f), fmaxf(x11, 0.f) };
                bf16 h[4], m[4], l[4];
#pragma unroll
                for (int q = 0; q < 4; q++) split3(hv[q], h[q], m[q], l[q]);
                *(__nv_bfloat162*)(g_H0 + r0 * N + c) = __nv_bfloat162(h[0], h[1]);
                *(__nv_bfloat162*)(g_H0 + r1 * N + c) = __nv_bfloat162(h[2], h[3]);
                *(__nv_bfloat162*)(g_H1 + r0 * N + c) = __nv_bfloat162(m[0], m[1]);
                *(__nv_bfloat162*)(g_H1 + r1 * N + c) = __nv_bfloat162(m[2], m[3]);
                *(__nv_bfloat162*)(g_H2 + r0 * N + c) = __nv_bfloat162(l[0], l[1]);
                *(__nv_bfloat162*)(g_H2 + r1 * N + c) = __nv_bfloat162(l[2], l[3]);
            } else {
                float2 f0 = *(const float2*)(F + r0 * N + c);
                float2 f1 = *(const float2*)(F + r1 * N + c);
                float g00 = f0.x * sigmoidf_(x00), g01 = f0.y * sigmoidf_(x01);
                float g10 = f1.x * sigmoidf_(x10), g11 = f1.y * sigmoidf_(x11);
                float2 o0, o1;
                o0.x = (g00 > 0.3f) ? 0.f : g00;  o0.y = (g01 > 0.3f) ? 0.f : g01;
                o1.x = (g10 > 0.3f) ? 0.f : g10;  o1.y = (g11 > 0.3f) ? 0.f : g11;
                *(float2*)(g_comp + r0 * N + c) = o0;
                *(float2*)(g_comp + r1 * N + c) = o1;
            }
        }
    }
#undef AS_
#undef BS_
}

// ---------------- row-wise post-processing ----------------------------------
#define R3 8

__global__ __launch_bounds__(256) void rowpost_k(
    const float* __restrict__ w_r1, const float* __restrict__ b_r1,
    const float* __restrict__ w_r2, const float* __restrict__ b_r2,
    const float* __restrict__ w_m1, const float* __restrict__ b_m1,
    const float* __restrict__ w_m2, const float* __restrict__ b_m2,
    float* __restrict__ out)
{
    const int tid  = threadIdx.x;
    const int lane = tid & 31;
    const int wid  = tid >> 5;

    __shared__ float sA[8], sB[8], sC[8], sD[8];

    float wr2[16][4];
#pragma unroll
    for (int k = 0; k < 16; k++)
#pragma unroll
        for (int j = 0; j < 4; j++)
            wr2[k][j] = __ldg(w_r2 + k * DIM + tid + 256 * j);
    float br2r[4];
#pragma unroll
    for (int j = 0; j < 4; j++) br2r[j] = __ldg(b_r2 + tid + 256 * j);

    for (int rr = 0; rr < R3; rr++) {
        size_t row = (size_t)blockIdx.x * R3 + rr;
        const float* cr = g_comp + row * DIM;

        __syncthreads();

        float v[4];
#pragma unroll
        for (int j = 0; j < 4; j++) v[j] = cr[tid + 256 * j];

        float cnt = 0.0f;
#pragma unroll
        for (int j = 0; j < 4; j++) cnt += (fabsf(v[j]) < 0.1f) ? 1.0f : 0.0f;
#pragma unroll
        for (int o = 16; o; o >>= 1) cnt += __shfl_xor_sync(0xffffffffu, cnt, o);
        if (lane == 0) sD[wid] = cnt;
        __syncthreads();
        cnt = 0.0f;
#pragma unroll
        for (int w = 0; w < 8; w++) cnt += sD[w];
        float cur_sp = cnt * (1.0f / 1024.0f);

        float hr[16];
#pragma unroll
        for (int k = 0; k < 16; k++) {
            float x = fmaf(cur_sp, __ldg(w_r1 + k),
                      fmaf(0.1f, __ldg(w_r1 + 16 + k), __ldg(b_r1 + k)));
            hr[k] = fmaxf(x, 0.0f);
        }

        float dyn[4];
        float s1 = 0.0f, s2 = 0.0f, mx = -INFINITY;
#pragma unroll
        for (int j = 0; j < 4; j++) {
            float a = br2r[j];
#pragma unroll
            for (int k = 0; k < 16; k++) a = fmaf(hr[k], wr2[k][j], a);
            float rw = sigmoidf_(a);
            float d  = v[j] * rw;
            dyn[j] = d;
            s1 += d;
            s2 = fmaf(d, d, s2);
            mx = fmaxf(mx, d);
        }
#pragma unroll
        for (int o = 16; o; o >>= 1) {
            s1 += __shfl_xor_sync(0xffffffffu, s1, o);
            s2 += __shfl_xor_sync(0xffffffffu, s2, o);
            mx = fmaxf(mx, __shfl_xor_sync(0xffffffffu, mx, o));
        }
        if (lane == 0) { sA[wid] = s1; sB[wid] = s2; sC[wid] = mx; }
        __syncthreads();
        s1 = 0.0f; s2 = 0.0f; mx = -INFINITY;
#pragma unroll
        for (int w = 0; w < 8; w++) {
            s1 += sA[w]; s2 += sB[w]; mx = fmaxf(mx, sC[w]);
        }

        float fmean = s1 * (1.0f / 1024.0f);
        float var   = (s2 - s1 * fmean) * (1.0f / 1023.0f);   // ddof=1
        var = fmaxf(var, 0.0f);
        float fstd = sqrtf(var);

        float a2 = __ldg(b_m2);
#pragma unroll
        for (int k = 0; k < 16; k++) {
            float x = fmaf(fmean, __ldg(w_m1 + k),
                      fmaf(fstd, __ldg(w_m1 + 16 + k),
                      fmaf(mx,   __ldg(w_m1 + 32 + k), __ldg(b_m1 + k))));
            a2 = fmaf(fmaxf(x, 0.0f), __ldg(w_m2 + k), a2);
        }
        float thr = sigmoidf_(a2);

        float* orow = out + row * DIM;
#pragma unroll
        for (int j = 0; j < 4; j++)
            orow[tid + 256 * j] = (fabsf(dyn[j]) > thr) ? dyn[j] : 0.0f;
    }
}

// ---------------- launch -----------------------------------------------------
extern "C" void kernel_launch(void* const* d_in, const int* in_sizes, int n_in,
                              void* d_out, int out_size)
{
    const float* F   = (const float*)d_in[0];
    const float* wg1 = (const float*)d_in[1];
    const float* bg1 = (const float*)d_in[2];
    const float* wg2 = (const float*)d_in[3];
    const float* bg2 = (const float*)d_in[4];
    // d_in[5..8] = competition weights: dead code (win == False always)
    const float* wr1 = (const float*)d_in[9];
    const float* br1 = (const float*)d_in[10];
    const float* wr2 = (const float*)d_in[11];
    const float* br2 = (const float*)d_in[12];
    const float* wm1 = (const float*)d_in[13];
    const float* bm1 = (const float*)d_in[14];
    const float* wm2 = (const float*)d_in[15];
    const float* bm2 = (const float*)d_in[16];
    float* out = (float*)d_out;
    (void)in_sizes; (void)n_in; (void)out_size;

    bf16 *W10, *W11, *W12, *W20, *W21, *W22, *F0, *F1, *F2, *H0, *H1, *H2;
    cudaGetSymbolAddress((void**)&W10, g_W10);
    cudaGetSymbolAddress((void**)&W11, g_W11);
    cudaGetSymbolAddress((void**)&W12, g_W12);
    cudaGetSymbolAddress((void**)&W20, g_W20);
    cudaGetSymbolAddress((void**)&W21, g_W21);
    cudaGetSymbolAddress((void**)&W22, g_W22);
    cudaGetSymbolAddress((void**)&F0, g_F0);
    cudaGetSymbolAddress((void**)&F1, g_F1);
    cudaGetSymbolAddress((void**)&F2, g_F2);
    cudaGetSymbolAddress((void**)&H0, g_H0);
    cudaGetSymbolAddress((void**)&H1, g_H1);
    cudaGetSymbolAddress((void**)&H2, g_H2);

    static int attr_done = 0;
    if (!attr_done) {
        cudaFuncSetAttribute(gemm_tc<0, DIM, HID>,
                             cudaFuncAttributeMaxDynamicSharedMemorySize, SMEM_BYTES);
        cudaFuncSetAttribute(gemm_tc<1, HID, DIM>,
                             cudaFuncAttributeMaxDynamicSharedMemorySize, SMEM_BYTES);
        attr_done = 1;
    }

    cvt_w_k<<<(DIM * HID + 255) / 256, 256>>>(wg1, W10, W11, W12, DIM, HID);
    cvt_w_k<<<(HID * DIM + 255) / 256, 256>>>(wg2, W20, W21, W22, HID, DIM);
    cvt_f_k<<<(BATCH * DIM / 4) / 256, 256>>>(F);

    // GEMM1: H = relu(F @ Wg1 + bg1)
    gemm_tc<0, DIM, HID><<<dim3(HID / BN, BATCH / BM), 256, SMEM_BYTES>>>(
        F0, F1, F2, W10, W11, W12, bg1, nullptr);
    // GEMM2: comp = thresh(F * sigmoid(H @ Wg2 + bg2))
    gemm_tc<1, HID, DIM><<<dim3(DIM / BN, BATCH / BM), 256, SMEM_BYTES>>>(
        H0, H1, H2, W20, W21, W22, bg2, F);
    // row-wise post-processing
    rowpost_k<<<BATCH / R3, 256>>>(wr1, br1, wr2, br2, wm1, bm1, wm2, bm2, out);
}